// round 4
// baseline (speedup 1.0000x reference)
#include <cuda_runtime.h>
#include <cuda_bf16.h>

// Problem constants
#define BATCH   32768
#define D       768          // 3*16*16 compressed features per sample
#define D4      192          // D/4
#define ROWS_PER_BLOCK 64
#define NBLOCKS (BATCH / ROWS_PER_BLOCK)   // 512
#define TP 17                // padded P-stride for T (bank-conflict-free)

// ---------------------------------------------------------------------------
// Fused kernel: each block folds lhs/rhs/W into W_eff (cheap, two-stage),
// then streams 64 rows of x doing out[n] = <x[n,:], W_eff> + b.
//
// Fold factorization:
//   T[ch,r,c,q,P]  = sum_Q rhs[c,q,Q] * W[ch,r*16+P,c*16+Q]   (1536 x 16 MAC)
//   Weff[ch,rr,cc] = sum_P lhs[r,P,p] * T[ch,r,c,q,P]          (768  x 16 MAC)
// Total ~36K MAC per block (~144 FMA/thread) - hidden under the DRAM stream.
// ---------------------------------------------------------------------------
__global__ __launch_bounds__(256)
void fused_kernel(const float4* __restrict__ x,    // [BATCH * D4]
                  const float*  __restrict__ lhs,  // [2,16,8]
                  const float*  __restrict__ rhs,  // [2,8,16]
                  const float*  __restrict__ W,    // [3072]
                  const float*  __restrict__ bptr, // [1]
                  float*        __restrict__ out)  // [BATCH]
{
    __shared__ float sLhs[256];
    __shared__ float sRhs[256];
    __shared__ float sT[96 * TP];        // [ch*2+r][c][q] x P (padded)
    __shared__ float sw[D];              // folded W_eff

    const int t = threadIdx.x;

    // Load the tiny operands to smem (L2-hot after block 0)
    sLhs[t] = lhs[t];
    sRhs[t] = rhs[t];
    __syncthreads();

    // ---- Fold stage 1: T[ch,r,c,q,P] = sum_Q rhs[c,q,Q] * W[...] ----
    #pragma unroll
    for (int i = 0; i < 6; i++) {
        const int idx = t + 256 * i;     // 0..1535
        const int P  = idx & 15;
        const int q  = (idx >> 4) & 7;
        const int c  = (idx >> 7) & 1;
        const int r  = (idx >> 8) & 1;
        const int ch = idx >> 9;
        const float* __restrict__ wrow = W + ch * 1024 + (r * 16 + P) * 32 + c * 16;
        const float* __restrict__ rrow = sRhs + c * 128 + q * 16;
        float s = 0.f;
        #pragma unroll
        for (int Q = 0; Q < 16; Q++)
            s = fmaf(rrow[Q], wrow[Q], s);
        sT[(((ch * 2 + r) * 2 + c) * 8 + q) * TP + P] = s;
    }
    __syncthreads();

    // ---- Fold stage 2: Weff[o] = sum_P lhs[r,P,p] * T[ch,r,c,q,P] ----
    #pragma unroll
    for (int i = 0; i < 3; i++) {
        const int o   = t + 256 * i;     // 0..767
        const int ch  = o >> 8;
        const int rem = o & 255;
        const int rr  = rem >> 4;
        const int cc  = rem & 15;
        const int r   = rr >> 3;
        const int p   = rr & 7;
        const int c   = cc >> 3;
        const int q   = cc & 7;
        const float* __restrict__ trow = sT + (((ch * 2 + r) * 2 + c) * 8 + q) * TP;
        const float* __restrict__ lcol = sLhs + r * 128 + p;
        float s = 0.f;
        #pragma unroll
        for (int P = 0; P < 16; P++)
            s = fmaf(lcol[P * 8], trow[P], s);
        sw[o] = s;
    }
    __syncthreads();

    // ---- GEMV: 8 warps x 2 rows x 4 iterations = 64 rows per block ----
    const int warp = t >> 5;
    const int lane = t & 31;
    const float bb = bptr[0];
    const float4* __restrict__ w4 = reinterpret_cast<const float4*>(sw);

    #pragma unroll
    for (int it = 0; it < 4; it++) {
        const int row0 = blockIdx.x * ROWS_PER_BLOCK + it * 16 + warp * 2;
        const float4* __restrict__ xr0 = x + (size_t)row0 * D4;
        const float4* __restrict__ xr1 = xr0 + D4;

        float a0 = 0.f, a1 = 0.f;
        #pragma unroll
        for (int k = 0; k < 6; k++) {
            const float4 v0 = __ldcs(&xr0[lane + k * 32]);
            const float4 v1 = __ldcs(&xr1[lane + k * 32]);
            const float4 w  = w4[lane + k * 32];
            a0 = fmaf(v0.x, w.x, a0);
            a0 = fmaf(v0.y, w.y, a0);
            a0 = fmaf(v0.z, w.z, a0);
            a0 = fmaf(v0.w, w.w, a0);
            a1 = fmaf(v1.x, w.x, a1);
            a1 = fmaf(v1.y, w.y, a1);
            a1 = fmaf(v1.z, w.z, a1);
            a1 = fmaf(v1.w, w.w, a1);
        }

        #pragma unroll
        for (int off = 16; off > 0; off >>= 1) {
            a0 += __shfl_xor_sync(0xFFFFFFFFu, a0, off);
            a1 += __shfl_xor_sync(0xFFFFFFFFu, a1, off);
        }

        if (lane == 0) {
            out[row0]     = a0 + bb;
            out[row0 + 1] = a1 + bb;
        }
    }
}

// ---------------------------------------------------------------------------
extern "C" void kernel_launch(void* const* d_in, const int* in_sizes, int n_in,
                              void* d_out, int out_size)
{
    const float* x   = (const float*)d_in[0];   // [32768, 3, 16, 16]
    const float* lhs = (const float*)d_in[1];   // [2, 16, 8]
    const float* rhs = (const float*)d_in[2];   // [2, 8, 16]
    const float* W   = (const float*)d_in[3];   // [1, 3072]
    const float* b   = (const float*)d_in[4];   // [1]
    float* out       = (float*)d_out;           // [32768]

    fused_kernel<<<NBLOCKS, 256>>>((const float4*)x, lhs, rhs, W, b, out);
}

// round 5
// speedup vs baseline: 1.0035x; 1.0035x over previous
#include <cuda_runtime.h>
#include <cuda_bf16.h>

// Problem constants
#define BATCH   32768
#define D       768          // 3*16*16 compressed features per sample
#define D4      192          // D/4
#define ROWS_PER_BLOCK 64
#define NBLOCKS (BATCH / ROWS_PER_BLOCK)   // 512
#define TP 17                // padded P-stride for T (bank-conflict-free)

// ---------------------------------------------------------------------------
// Fused kernel: each block folds lhs/rhs/W into W_eff (cheap, two-stage),
// then streams 64 rows of x doing out[n] = <x[n,:], W_eff> + b.
//
// Fold factorization:
//   T[ch,r,c,q,P]  = sum_Q rhs[c,q,Q] * W[ch,r*16+P,c*16+Q]   (1536 x 16 MAC)
//   Weff[ch,rr,cc] = sum_P lhs[r,P,p] * T[ch,r,c,q,P]          (768  x 16 MAC)
// Total ~36K MAC per block (~144 FMA/thread) - hidden under the DRAM stream.
// ---------------------------------------------------------------------------
__global__ __launch_bounds__(256)
void fused_kernel(const float4* __restrict__ x,    // [BATCH * D4]
                  const float*  __restrict__ lhs,  // [2,16,8]
                  const float*  __restrict__ rhs,  // [2,8,16]
                  const float*  __restrict__ W,    // [3072]
                  const float*  __restrict__ bptr, // [1]
                  float*        __restrict__ out)  // [BATCH]
{
    __shared__ float sLhs[256];
    __shared__ float sRhs[256];
    __shared__ float sT[96 * TP];        // [ch*2+r][c][q] x P (padded)
    __shared__ float sw[D];              // folded W_eff

    const int t = threadIdx.x;

    // Load the tiny operands to smem (L2-hot after block 0)
    sLhs[t] = lhs[t];
    sRhs[t] = rhs[t];
    __syncthreads();

    // ---- Fold stage 1: T[ch,r,c,q,P] = sum_Q rhs[c,q,Q] * W[...] ----
    #pragma unroll
    for (int i = 0; i < 6; i++) {
        const int idx = t + 256 * i;     // 0..1535
        const int P  = idx & 15;
        const int q  = (idx >> 4) & 7;
        const int c  = (idx >> 7) & 1;
        const int r  = (idx >> 8) & 1;
        const int ch = idx >> 9;
        const float* __restrict__ wrow = W + ch * 1024 + (r * 16 + P) * 32 + c * 16;
        const float* __restrict__ rrow = sRhs + c * 128 + q * 16;
        float s = 0.f;
        #pragma unroll
        for (int Q = 0; Q < 16; Q++)
            s = fmaf(rrow[Q], wrow[Q], s);
        sT[(((ch * 2 + r) * 2 + c) * 8 + q) * TP + P] = s;
    }
    __syncthreads();

    // ---- Fold stage 2: Weff[o] = sum_P lhs[r,P,p] * T[ch,r,c,q,P] ----
    #pragma unroll
    for (int i = 0; i < 3; i++) {
        const int o   = t + 256 * i;     // 0..767
        const int ch  = o >> 8;
        const int rem = o & 255;
        const int rr  = rem >> 4;
        const int cc  = rem & 15;
        const int r   = rr >> 3;
        const int p   = rr & 7;
        const int c   = cc >> 3;
        const int q   = cc & 7;
        const float* __restrict__ trow = sT + (((ch * 2 + r) * 2 + c) * 8 + q) * TP;
        const float* __restrict__ lcol = sLhs + r * 128 + p;
        float s = 0.f;
        #pragma unroll
        for (int P = 0; P < 16; P++)
            s = fmaf(lcol[P * 8], trow[P], s);
        sw[o] = s;
    }
    __syncthreads();

    // ---- GEMV: 8 warps x 2 rows x 4 iterations = 64 rows per block ----
    const int warp = t >> 5;
    const int lane = t & 31;
    const float bb = bptr[0];
    const float4* __restrict__ w4 = reinterpret_cast<const float4*>(sw);

    #pragma unroll
    for (int it = 0; it < 4; it++) {
        const int row0 = blockIdx.x * ROWS_PER_BLOCK + it * 16 + warp * 2;
        const float4* __restrict__ xr0 = x + (size_t)row0 * D4;
        const float4* __restrict__ xr1 = xr0 + D4;

        float a0 = 0.f, a1 = 0.f;
        #pragma unroll
        for (int k = 0; k < 6; k++) {
            const float4 v0 = __ldcs(&xr0[lane + k * 32]);
            const float4 v1 = __ldcs(&xr1[lane + k * 32]);
            const float4 w  = w4[lane + k * 32];
            a0 = fmaf(v0.x, w.x, a0);
            a0 = fmaf(v0.y, w.y, a0);
            a0 = fmaf(v0.z, w.z, a0);
            a0 = fmaf(v0.w, w.w, a0);
            a1 = fmaf(v1.x, w.x, a1);
            a1 = fmaf(v1.y, w.y, a1);
            a1 = fmaf(v1.z, w.z, a1);
            a1 = fmaf(v1.w, w.w, a1);
        }

        #pragma unroll
        for (int off = 16; off > 0; off >>= 1) {
            a0 += __shfl_xor_sync(0xFFFFFFFFu, a0, off);
            a1 += __shfl_xor_sync(0xFFFFFFFFu, a1, off);
        }

        if (lane == 0) {
            out[row0]     = a0 + bb;
            out[row0 + 1] = a1 + bb;
        }
    }
}

// ---------------------------------------------------------------------------
extern "C" void kernel_launch(void* const* d_in, const int* in_sizes, int n_in,
                              void* d_out, int out_size)
{
    const float* x   = (const float*)d_in[0];   // [32768, 3, 16, 16]
    const float* lhs = (const float*)d_in[1];   // [2, 16, 8]
    const float* rhs = (const float*)d_in[2];   // [2, 8, 16]
    const float* W   = (const float*)d_in[3];   // [1, 3072]
    const float* b   = (const float*)d_in[4];   // [1]
    float* out       = (float*)d_out;           // [32768]

    fused_kernel<<<NBLOCKS, 256>>>((const float4*)x, lhs, rhs, W, b, out);
}